// round 8
// baseline (speedup 1.0000x reference)
#include <cuda_runtime.h>
#include <cuda_bf16.h>

// Problem constants (fixed shapes from reference setup_inputs)
#define NB     307              // N nodes
#define SSUB   4                // S subgraphs
#define MTOT   (NB * SSUB)      // 1228 embedding rows (even -> 614 per parity)
#define RHALF  614              // rows per parity slice
#define TT     12               // T
#define BBAT   16               // B
#define BT     (BBAT * TT)      // 192 effective batch
#define CC     64               // channels
#define MAXE   64               // max total entries per row (actual <= 44)
#define MAXP   48               // max entries per (row,parity)  (provably <= 42)
#define QROWS  77               // rows per quarter (77,77,77,76)
#define NUNITS (BT * 2 * 4)     // 1536 units: (bt, parity, quarter)
#define TMAIN  384              // threads in k_main (12 warps)
#define NWMAIN 12

#define EMB_B   (RHALF * CC * 2)      // 78,592  parity emb slice (bf16)
#define SNM_B   (QROWS * CC * 4)      // 19,712  nm rows fp32
#define META_B  (QROWS * MAXP * 2)    // 7,392
#define CNT_B   (QROWS * 4 + 12)      // 320
#define SMEM_BYTES (EMB_B + SNM_B + META_B + CNT_B)   // 106,016

#define NORM_BLOCKS 7368   // ceil(16*307*12 / 8 warps)
#define MASK_BLOCKS 39     // ceil(307 / 8 warps-per-block)

// Scratch (static device allocations — no runtime alloc)
__device__ __nv_bfloat16 g_embT[(size_t)BT * 2 * RHALF * CC]; // [bt][par][r][c], ~30 MB
__device__ int           g_cnt2[NB * 2];
__device__ __align__(16) unsigned short g_pk2[NB * 2 * MAXP]; // r(10b)|pos<<11|dbl<<12, dealt
__device__ float         g_num[2 * BT * NB];                  // [par][bt][n]
__device__ float         g_den[2 * BT * NB];
__device__ float         g_partial[BT];
__device__ int           g_done;

__device__ __forceinline__ float bf_lo(unsigned u) { return __uint_as_float(u << 16); }
__device__ __forceinline__ float bf_hi(unsigned u) { return __uint_as_float(u & 0xffff0000u); }

__device__ __forceinline__ unsigned smem_u32(const void* p) {
    return (unsigned)__cvta_generic_to_shared(p);
}
__device__ __forceinline__ void cp16(unsigned dst, const void* src) {
    asm volatile("cp.async.cg.shared.global [%0], [%1], 16;" :: "r"(dst), "l"(src));
}

// ---------------------------------------------------------------------------
// Kernel 1 (fused): role A = normalize subgraph emb -> g_embT[bt][par][r][c];
// role B = build per-(n,parity) packed entry lists, bank-dealt by (m>>1)&7 so
// k_main's LDS.128 phases are conflict-free. Also resets the done counter.
// ---------------------------------------------------------------------------
__global__ void k_prep(const float* __restrict__ se,
                       const float* __restrict__ pos,
                       const float* __restrict__ neg) {
    if (blockIdx.x < NORM_BLOCKS) {
        int warp = (blockIdx.x * blockDim.x + threadIdx.x) >> 5;
        int lane = threadIdx.x & 31;
        if (warp >= BBAT * NB * TT) return;
        int t  = warp % TT;
        int bj = warp / TT;
        int j  = bj % NB;
        int b  = bj / NB;
        int bt = b * TT + t;

        const float4* src = (const float4*)(se) + (size_t)warp * CC;
        float4 v0 = src[2 * lane];       // channel c0=2*lane, comps s0..s3
        float4 v1 = src[2 * lane + 1];

        float ss0 = v0.x * v0.x + v1.x * v1.x;
        float ss1 = v0.y * v0.y + v1.y * v1.y;
        float ss2 = v0.z * v0.z + v1.z * v1.z;
        float ss3 = v0.w * v0.w + v1.w * v1.w;
        #pragma unroll
        for (int off = 16; off; off >>= 1) {
            ss0 += __shfl_xor_sync(0xffffffffu, ss0, off);
            ss1 += __shfl_xor_sync(0xffffffffu, ss1, off);
            ss2 += __shfl_xor_sync(0xffffffffu, ss2, off);
            ss3 += __shfl_xor_sync(0xffffffffu, ss3, off);
        }
        float sc0 = rsqrtf(fmaxf(ss0, 1e-24f));
        float sc1 = rsqrtf(fmaxf(ss1, 1e-24f));
        float sc2 = rsqrtf(fmaxf(ss2, 1e-24f));
        float sc3 = rsqrtf(fmaxf(ss3, 1e-24f));

        // m = s*NB + j -> parity = m&1, r = m>>1
        #pragma unroll
        for (int s = 0; s < SSUB; s++) {
            int m = s * NB + j;
            float sc = (s == 0) ? sc0 : (s == 1) ? sc1 : (s == 2) ? sc2 : sc3;
            float lo = ((s == 0) ? v0.x : (s == 1) ? v0.y : (s == 2) ? v0.z : v0.w) * sc;
            float hi = ((s == 0) ? v1.x : (s == 1) ? v1.y : (s == 2) ? v1.z : v1.w) * sc;
            __nv_bfloat162* dst = (__nv_bfloat162*)(g_embT
                + (((size_t)(bt * 2 + (m & 1)) * RHALF + (m >> 1)) * CC)) + lane;
            *dst = __floats2bfloat162_rn(lo, hi);
        }
    } else {
        // mask role: warp w of block handles n = (blk-NORM)*8 + w
        __shared__ unsigned short buf[8][MAXE];   // r | pos<<11 | dbl<<12 | par<<13
        __shared__ unsigned short key[8][MAXE];
        int mb = blockIdx.x - NORM_BLOCKS;
        int wid = threadIdx.x >> 5, lane = threadIdx.x & 31;
        if (mb == 0 && threadIdx.x == 0) g_done = 0;
        int n = mb * 8 + wid;
        if (n >= NB) return;
        int base = 0;
        for (int m0 = 0; m0 < MTOT; m0 += 32) {
            int m = m0 + lane;
            float p = 0.0f, q = 0.0f;
            if (m < MTOT) {
                p = pos[(size_t)n * MTOT + m];
                q = neg[(size_t)n * MTOT + m];
            }
            float w = p + q;
            unsigned bal = __ballot_sync(0xffffffffu, w > 0.0f);
            if (w > 0.0f) {
                int i = base + __popc(bal & ((1u << lane) - 1u));
                if (i < MAXE) {
                    buf[wid][i] = (unsigned short)((m >> 1)
                        | ((p > 0.5f) ? 2048 : 0)
                        | ((w > 1.5f) ? 4096 : 0)
                        | ((m & 1) << 13));
                }
            }
            base += __popc(bal);
        }
        int cnt = min(base, MAXE);
        __syncwarp();

        #pragma unroll
        for (int par = 0; par < 2; par++) {
            // unique key = rank_within_bucket*8 + bucket, bucket = r&7
            #pragma unroll
            for (int h = 0; h < 2; h++) {
                int i = lane + h * 32;
                if (i < cnt && ((buf[wid][i] >> 13) & 1) == par) {
                    int bucket = buf[wid][i] & 7;
                    int rk = 0;
                    for (int j2 = 0; j2 < i; j2++)
                        rk += (((buf[wid][j2] >> 13) & 1) == par) &&
                              ((buf[wid][j2] & 7) == bucket);
                    key[wid][i] = (unsigned short)(rk * 8 + bucket);
                }
            }
            __syncwarp();
            // scatter by key rank among same-parity entries; count
            int myc = 0;
            #pragma unroll
            for (int h = 0; h < 2; h++) {
                int i = lane + h * 32;
                if (i < cnt && ((buf[wid][i] >> 13) & 1) == par) {
                    int ky = key[wid][i];
                    int p2 = 0;
                    for (int j2 = 0; j2 < cnt; j2++)
                        p2 += (((buf[wid][j2] >> 13) & 1) == par) &&
                              (key[wid][j2] < ky);
                    if (p2 < MAXP)
                        g_pk2[(n * 2 + par) * MAXP + p2] =
                            (unsigned short)(buf[wid][i] & 0x1FFF);
                }
                // count parity entries (each lane counts its own flags)
                if (i < cnt) myc += (((buf[wid][i] >> 13) & 1) == par);
            }
            #pragma unroll
            for (int off = 16; off; off >>= 1)
                myc += __shfl_xor_sync(0xffffffffu, myc, off);
            if (lane == 0) g_cnt2[n * 2 + par] = min(myc, MAXP);
            __syncwarp();
        }
    }
}

// ---------------------------------------------------------------------------
// Kernel 2: main SDDMM. 1536 blocks = (bt, parity, quarter); 2 CTAs/SM.
// cp.async-fills: semb (614-row parity emb slice, XOR-swizzled by r&7),
// snm (fp32 nm rows), smeta (dealt entry lists), scnt. Hot loop: channel-
// phased dot (A-low then A-high, 32 regs) over each lane's <=2 entries;
// conflict-free LDS.128; per-row shfl-reduced num/den -> g_num/g_den.
// ---------------------------------------------------------------------------
__global__ void __launch_bounds__(TMAIN, 2) k_main(const float* __restrict__ node_mem) {
    extern __shared__ __align__(16) char smraw[];
    uint4*          semb  = (uint4*)smraw;                       // RHALF*8 uint4
    float*          snm   = (float*)(smraw + EMB_B);
    unsigned short* smeta = (unsigned short*)(smraw + EMB_B + SNM_B);
    int*            scnt  = (int*)(smraw + EMB_B + SNM_B + META_B);

    int u = blockIdx.x;
    int bt = u >> 3;
    int parity = (u >> 2) & 1;
    int quarter = u & 3;
    int b = bt / TT, t = bt % TT;
    int n0 = quarter * QROWS;
    int rows = (quarter == 3) ? (NB - 3 * QROWS) : QROWS;

    // --- cp.async fill phase -------------------------------------------------
    {
        const uint4* esrc = (const uint4*)(g_embT)
                          + (size_t)(bt * 2 + parity) * RHALF * 8;
        for (int idx = threadIdx.x; idx < RHALF * 8; idx += TMAIN) {
            int r = idx >> 3, w = idx & 7;
            cp16(smem_u32(&semb[(r << 3) | (w ^ (r & 7))]), esrc + idx);
        }
    }
    for (int idx = threadIdx.x; idx < rows * 16; idx += TMAIN) {
        int rr = idx >> 4, seg = idx & 15;
        const char* src = (const char*)(node_mem
            + (((size_t)b * NB + (n0 + rr)) * TT + t) * CC) + seg * 16;
        cp16(smem_u32((char*)snm + rr * 256 + seg * 16), src);
    }
    for (int idx = threadIdx.x; idx < rows * 6; idx += TMAIN) {   // 96 B per row
        int rr = idx / 6, seg = idx % 6;
        const char* src = (const char*)(g_pk2)
            + ((size_t)((n0 + rr) * 2 + parity)) * (MAXP * 2) + seg * 16;
        cp16(smem_u32((char*)smeta + rr * 96 + seg * 16), src);
    }
    if (threadIdx.x < rows) scnt[threadIdx.x] = g_cnt2[(n0 + threadIdx.x) * 2 + parity];
    asm volatile("cp.async.commit_group;");
    asm volatile("cp.async.wait_group 0;");
    __syncthreads();

    // --- compute phase -------------------------------------------------------
    int wid = threadIdx.x >> 5, lane = threadIdx.x & 31;

    for (int i = wid; i < rows; i += NWMAIN) {
        int cnt = scnt[i];
        unsigned pk0 = 0xFFFFu, pk1 = 0xFFFFu;
        if (lane < cnt)      pk0 = smeta[i * MAXP + lane];
        if (lane + 32 < cnt) pk1 = smeta[i * MAXP + lane + 32];
        int r0 = pk0 & 1023, sw0 = r0 & 7;
        int r1 = pk1 & 1023, sw1 = r1 & 7;
        const float4* ap = (const float4*)(snm + i * CC);
        float dot0 = 0.0f, dot1 = 0.0f;

        // phase 0: channels 0..31 (logical chunks 0..3)
        {
            float4 A[8];
            #pragma unroll
            for (int k = 0; k < 8; k++) A[k] = ap[k];
            if (pk0 != 0xFFFFu) {
                const uint4* ep = semb + (r0 << 3);
                #pragma unroll
                for (int w = 0; w < 4; w++) {
                    uint4 q = ep[w ^ sw0];
                    float4 A0 = A[2 * w], A1 = A[2 * w + 1];
                    dot0 = fmaf(A0.x, bf_lo(q.x), dot0);
                    dot0 = fmaf(A0.y, bf_hi(q.x), dot0);
                    dot0 = fmaf(A0.z, bf_lo(q.y), dot0);
                    dot0 = fmaf(A0.w, bf_hi(q.y), dot0);
                    dot0 = fmaf(A1.x, bf_lo(q.z), dot0);
                    dot0 = fmaf(A1.y, bf_hi(q.z), dot0);
                    dot0 = fmaf(A1.z, bf_lo(q.w), dot0);
                    dot0 = fmaf(A1.w, bf_hi(q.w), dot0);
                }
            }
            if (pk1 != 0xFFFFu) {
                const uint4* ep = semb + (r1 << 3);
                #pragma unroll
                for (int w = 0; w < 4; w++) {
                    uint4 q = ep[w ^ sw1];
                    float4 A0 = A[2 * w], A1 = A[2 * w + 1];
                    dot1 = fmaf(A0.x, bf_lo(q.x), dot1);
                    dot1 = fmaf(A0.y, bf_hi(q.x), dot1);
                    dot1 = fmaf(A0.z, bf_lo(q.y), dot1);
                    dot1 = fmaf(A0.w, bf_hi(q.y), dot1);
                    dot1 = fmaf(A1.x, bf_lo(q.z), dot1);
                    dot1 = fmaf(A1.y, bf_hi(q.z), dot1);
                    dot1 = fmaf(A1.z, bf_lo(q.w), dot1);
                    dot1 = fmaf(A1.w, bf_hi(q.w), dot1);
                }
            }
        }
        // phase 1: channels 32..63 (logical chunks 4..7)
        {
            float4 A[8];
            #pragma unroll
            for (int k = 0; k < 8; k++) A[k] = ap[8 + k];
            if (pk0 != 0xFFFFu) {
                const uint4* ep = semb + (r0 << 3);
                #pragma unroll
                for (int w = 4; w < 8; w++) {
                    uint4 q = ep[w ^ sw0];
                    float4 A0 = A[2 * (w - 4)], A1 = A[2 * (w - 4) + 1];
                    dot0 = fmaf(A0.x, bf_lo(q.x), dot0);
                    dot0 = fmaf(A0.y, bf_hi(q.x), dot0);
                    dot0 = fmaf(A0.z, bf_lo(q.y), dot0);
                    dot0 = fmaf(A0.w, bf_hi(q.y), dot0);
                    dot0 = fmaf(A1.x, bf_lo(q.z), dot0);
                    dot0 = fmaf(A1.y, bf_hi(q.z), dot0);
                    dot0 = fmaf(A1.z, bf_lo(q.w), dot0);
                    dot0 = fmaf(A1.w, bf_hi(q.w), dot0);
                }
            }
            if (pk1 != 0xFFFFu) {
                const uint4* ep = semb + (r1 << 3);
                #pragma unroll
                for (int w = 4; w < 8; w++) {
                    uint4 q = ep[w ^ sw1];
                    float4 A0 = A[2 * (w - 4)], A1 = A[2 * (w - 4) + 1];
                    dot1 = fmaf(A0.x, bf_lo(q.x), dot1);
                    dot1 = fmaf(A0.y, bf_hi(q.x), dot1);
                    dot1 = fmaf(A0.z, bf_lo(q.y), dot1);
                    dot1 = fmaf(A0.w, bf_hi(q.y), dot1);
                    dot1 = fmaf(A1.x, bf_lo(q.z), dot1);
                    dot1 = fmaf(A1.y, bf_hi(q.z), dot1);
                    dot1 = fmaf(A1.z, bf_lo(q.w), dot1);
                    dot1 = fmaf(A1.w, bf_hi(q.w), dot1);
                }
            }
        }

        float ex0 = (pk0 != 0xFFFFu) ? __expf(dot0 * 2.0f) : 0.0f;
        float ex1 = (pk1 != 0xFFFFu) ? __expf(dot1 * 2.0f) : 0.0f;
        float num = ((pk0 & 2048) ? ex0 : 0.0f) + ((pk1 & 2048) ? ex1 : 0.0f);
        float den = ex0 + ex1
                  + ((pk0 & 4096) ? ex0 : 0.0f) + ((pk1 & 4096) ? ex1 : 0.0f);
        #pragma unroll
        for (int off = 16; off; off >>= 1) {
            num += __shfl_xor_sync(0xffffffffu, num, off);
            den += __shfl_xor_sync(0xffffffffu, den, off);
        }
        if (lane == 0) {
            size_t o = ((size_t)parity * BT + bt) * NB + (n0 + i);
            g_num[o] = num;
            g_den[o] = den;
        }
    }
}

// ---------------------------------------------------------------------------
// Kernel 3: combine parities, log, per-bt reduce; last block -> scalar loss.
// ---------------------------------------------------------------------------
__global__ void __launch_bounds__(320) k_post(float* __restrict__ out) {
    int bt = blockIdx.x;
    int tid = threadIdx.x;
    float v = 0.0f;
    if (tid < NB) {
        size_t o0 = (size_t)bt * NB + tid;
        size_t o1 = (size_t)(BT + bt) * NB + tid;
        float num = g_num[o0] + g_num[o1];
        float den = g_den[o0] + g_den[o1];
        v = __logf(num / (den + 1e-12f));
    }
    #pragma unroll
    for (int off = 16; off; off >>= 1)
        v += __shfl_xor_sync(0xffffffffu, v, off);
    __shared__ float wsum[10];
    __shared__ int s_last;
    if ((tid & 31) == 0) wsum[tid >> 5] = v;
    __syncthreads();
    if (tid == 0) {
        float s = 0.0f;
        #pragma unroll
        for (int k = 0; k < 10; k++) s += wsum[k];
        g_partial[bt] = s;
        __threadfence();
        int prev = atomicAdd(&g_done, 1);
        s_last = (prev == BT - 1) ? 1 : 0;
    }
    __syncthreads();
    if (s_last && tid == 0) {
        volatile float* gp = g_partial;
        float s = 0.0f;
        for (int k = 0; k < BT; k++) s += gp[k];
        out[0] = -s / (float)(BT * NB);
        g_done = 0;   // restore for next graph replay
    }
}

// ---------------------------------------------------------------------------
extern "C" void kernel_launch(void* const* d_in, const int* in_sizes, int n_in,
                              void* d_out, int out_size) {
    const float* node_memory = (const float*)d_in[0];   // [16,307,12,64]
    const float* subgraph    = (const float*)d_in[1];   // [16,307,12,64,4]
    const float* pos_mask    = (const float*)d_in[2];   // [307,1228]
    const float* neg_mask    = (const float*)d_in[3];   // [307,1228]
    float* out = (float*)d_out;

    cudaFuncSetAttribute(k_main, cudaFuncAttributeMaxDynamicSharedMemorySize,
                         SMEM_BYTES);

    // Kernel 1: normalize (7368 blocks) + per-parity dealt masks (39 blocks)
    k_prep<<<NORM_BLOCKS + MASK_BLOCKS, 256>>>(subgraph, pos_mask, neg_mask);

    // Kernel 2: (bt, parity, quarter) units, 2 CTAs/SM
    k_main<<<NUNITS, TMAIN, SMEM_BYTES>>>(node_memory);

    // Kernel 3: combine + log + reduce -> scalar
    k_post<<<BT, 320>>>(out);
}